// round 6
// baseline (speedup 1.0000x reference)
#include <cuda_runtime.h>
#include <cuda_fp16.h>
#include <cstdint>

// ============================================================================
// y[m,n] = sum_k x[m,k] * ((q[k,n]-zp)*scale) + bias[n]
// Decomposition: W = scale*(q-128) + scale*(128-zp);  (q-128) exact in fp16.
//   acc = half(x) @ half(q-128)   (fp32 accum via mma.sync HMMA)
//   y = scale*acc + scale*(128-zp)*rowsum(x)[m] + bias[n]
// R6 (= R5 resubmit; container infra failed): wave-quantization fix.
//   1024 tiles over n_conc=296 was 3.46 waves (86.5% ceiling). Now:
//   512-thread CTA, 1 CTA/SM, 128x128 tile, 6-stage pipeline ->
//   1024/148 = 6.92 waves (98.9%). Same 16 warps/SM as R4.
// ============================================================================

#define M_TOT 4096
#define N_TOT 4096
#define K_TOT 4096

__device__ __align__(256) __half g_A[(size_t)M_TOT * K_TOT]; // x fp16 [M,K]
__device__ __align__(256) __half g_B[(size_t)N_TOT * K_TOT]; // (q-128) fp16 [N,K]
__device__ float g_rowsum[M_TOT];

// ---------------------------------------------------------------------------
__device__ __forceinline__ uint32_t smem_to_u32(const void* p) {
    uint32_t a;
    asm("{ .reg .u64 t; cvta.to.shared.u64 t, %1; cvt.u32.u64 %0, t; }"
        : "=r"(a) : "l"(p));
    return a;
}

#define SWZ(o) ((o) ^ (((o) >> 3) & 0x70))

#define CP_ASYNC_16(dst, src) \
    asm volatile("cp.async.cg.shared.global [%0], [%1], 16;" \
                 :: "r"(dst), "l"(src) : "memory")
#define CP_COMMIT() asm volatile("cp.async.commit_group;" ::: "memory")
#define CP_WAIT(n)  asm volatile("cp.async.wait_group %0;" :: "n"(n) : "memory")

#define LDSM_X4(R0, R1, R2, R3, ADDR) \
    asm volatile("ldmatrix.sync.aligned.m8n8.x4.shared.b16 {%0,%1,%2,%3}, [%4];" \
                 : "=r"(R0), "=r"(R1), "=r"(R2), "=r"(R3) : "r"(ADDR))

#define MMA16816(C, A0, A1, A2, A3, B0, B1) \
    asm volatile("mma.sync.aligned.m16n8k16.row.col.f32.f16.f16.f32 " \
                 "{%0,%1,%2,%3}, {%4,%5,%6,%7}, {%8,%9}, {%0,%1,%2,%3};" \
                 : "+f"((C)[0]), "+f"((C)[1]), "+f"((C)[2]), "+f"((C)[3]) \
                 : "r"(A0), "r"(A1), "r"(A2), "r"(A3), "r"(B0), "r"(B1))

// ---------------------------------------------------------------------------
// Merged prep: blocks [0,4096) convert x rows + rowsum; blocks [4096, 20480)
// transpose+convert 32x32 tiles of W.
// ---------------------------------------------------------------------------
__global__ void prep_kernel(const float* __restrict__ x,
                            const int* __restrict__ W) {
    __shared__ float red[256];
    __shared__ __half tile[32][33];
    const int tid = threadIdx.x;

    if (blockIdx.x < M_TOT) {
        const int m = blockIdx.x;
        const float4* xr = reinterpret_cast<const float4*>(x + (size_t)m * K_TOT);
        __half2* ar = reinterpret_cast<__half2*>(g_A + (size_t)m * K_TOT);
        float s = 0.0f;
        for (int i = tid; i < K_TOT / 4; i += 256) {
            float4 v = xr[i];
            ar[2 * i]     = __floats2half2_rn(v.x, v.y);
            ar[2 * i + 1] = __floats2half2_rn(v.z, v.w);
            s += (v.x + v.y) + (v.z + v.w);
        }
        red[tid] = s;
        __syncthreads();
        for (int o = 128; o > 0; o >>= 1) {
            if (tid < o) red[tid] += red[tid + o];
            __syncthreads();
        }
        if (tid == 0) g_rowsum[m] = red[0];
    } else {
        const int t  = blockIdx.x - M_TOT;
        const int n0 = (t & (N_TOT / 32 - 1)) * 32;
        const int k0 = (t >> 7) * 32;
        const int tx = tid & 31, ty = tid >> 5;  // 32 x 8
        #pragma unroll
        for (int j = 0; j < 32; j += 8) {
            int k = k0 + ty + j;
            int n = n0 + tx;
            tile[ty + j][tx] = __int2half_rn(W[(size_t)k * N_TOT + n] - 128);
        }
        __syncthreads();
        #pragma unroll
        for (int j = 0; j < 32; j += 8) {
            int n = n0 + ty + j;
            int k = k0 + tx;
            g_B[(size_t)n * K_TOT + k] = tile[tx][ty + j];
        }
    }
}

// ---------------------------------------------------------------------------
// GEMM: BM=128, BN=128, BK=64, 6-stage cp.async, 512 threads, 1 CTA/SM.
// Warp grid 4(M) x 4(N); warp tile 32x32; mma.sync m16n8k16 f32 accum.
// ---------------------------------------------------------------------------
static constexpr int BM = 128;
static constexpr int BN = 128;
static constexpr int BK = 64;           // 128 bytes per row
static constexpr int STAGES = 6;
static constexpr int NCHUNK = K_TOT / BK;                // 64
static constexpr int A_BYTES   = BM * 128;               // 16384
static constexpr int B_BYTES   = BN * 128;               // 16384
static constexpr int STG_BYTES = A_BYTES + B_BYTES;      // 32768
static constexpr int DYN_SMEM  = 1024 + STAGES * STG_BYTES;  // 197632
static constexpr int A_JOBS = BM * 8;                    // 1024 x 16B
static constexpr int JOBS   = (BM + BN) * 8;             // 2048 x 16B
static constexpr int NTHREADS = 512;

__global__ __launch_bounds__(NTHREADS, 1)
void gemm_kernel(const float* __restrict__ scale_p,
                 const float* __restrict__ zp_p,
                 const float* __restrict__ bias,
                 float* __restrict__ out) {
    extern __shared__ char dyn_smem[];
    const uint32_t base = (smem_to_u32(dyn_smem) + 1023u) & ~1023u;

    const int tid  = threadIdx.x;
    const int lane = tid & 31;
    const int wid  = tid >> 5;          // 0..15
    const int warpM = wid & 3;          // 0..3 (32 rows each)
    const int warpN = wid >> 2;         // 0..3 (32 cols each)

    const __half* Abase = g_A + (size_t)(blockIdx.y * BM) * K_TOT;
    const __half* Bbase = g_B + (size_t)(blockIdx.x * BN) * K_TOT;

    const int rowA = lane & 15;                       // A rows within m16
    const int khA  = (lane >> 4) * 8;                 // A k-half
    const int rowB = (lane & 7) + ((lane & 16) >> 1); // B n within n16
    const int khB  = ((lane >> 3) & 1) * 8;           // B k-half

    float acc[2][4][4];  // [mt 2 x m16][nt 4 x n8][frag]
    #pragma unroll
    for (int i = 0; i < 2; i++)
        #pragma unroll
        for (int j = 0; j < 4; j++)
            #pragma unroll
            for (int t = 0; t < 4; t++) acc[i][j][t] = 0.0f;

    auto load_stage = [&](int c, int st) {
        const int kofs = c * BK;
        const uint32_t sa = base + (uint32_t)st * STG_BYTES;
        const uint32_t sb = sa + A_BYTES;
        #pragma unroll
        for (int j = tid; j < JOBS; j += NTHREADS) {
            if (j < A_JOBS) {
                int r = j >> 3, cc = j & 7;
                uint32_t dst = sa + SWZ((uint32_t)(r * 128 + cc * 16));
                CP_ASYNC_16(dst, Abase + (size_t)r * K_TOT + kofs + cc * 8);
            } else {
                int jj = j - A_JOBS;
                int r = jj >> 3, cc = jj & 7;
                uint32_t dst = sb + SWZ((uint32_t)(r * 128 + cc * 16));
                CP_ASYNC_16(dst, Bbase + (size_t)r * K_TOT + kofs + cc * 8);
            }
        }
    };

    // prologue: fill STAGES-1 = 5 stages
    #pragma unroll
    for (int s = 0; s < STAGES - 1; s++) {
        load_stage(s, s);
        CP_COMMIT();
    }

    int st = 0, pst = STAGES - 1;
    for (int c = 0; c < NCHUNK; c++) {
        CP_WAIT(STAGES - 2);
        __syncthreads();   // all reads of stage pst (chunk c-1) complete

        if (c + STAGES - 1 < NCHUNK) load_stage(c + STAGES - 1, pst);
        CP_COMMIT();

        const uint32_t sa = base + (uint32_t)st * STG_BYTES;
        const uint32_t sb = sa + A_BYTES;

        #pragma unroll
        for (int ks = 0; ks < 4; ks++) {
            uint32_t b[2][4];
            #pragma unroll
            for (int q = 0; q < 2; q++) {
                uint32_t off = (uint32_t)((warpN * 32 + q * 16 + rowB) * 128 +
                                          (ks * 16 + khB) * 2);
                LDSM_X4(b[q][0], b[q][1], b[q][2], b[q][3], sb + SWZ(off));
            }
            #pragma unroll
            for (int mt = 0; mt < 2; mt++) {
                uint32_t a0, a1, a2, a3;
                uint32_t off = (uint32_t)((warpM * 32 + mt * 16 + rowA) * 128 +
                                          (ks * 16 + khA) * 2);
                LDSM_X4(a0, a1, a2, a3, sa + SWZ(off));
                #pragma unroll
                for (int q = 0; q < 2; q++) {
                    MMA16816(acc[mt][2 * q],     a0, a1, a2, a3, b[q][0], b[q][1]);
                    MMA16816(acc[mt][2 * q + 1], a0, a1, a2, a3, b[q][2], b[q][3]);
                }
            }
        }
        pst = st;
        st = (st + 1 == STAGES) ? 0 : st + 1;
        // next iteration's wait+sync protects stage reuse
    }

    // ---- epilogue ----
    const float scale = scale_p[0];
    const float zp    = zp_p[0];
    const float kz    = scale * (128.0f - zp);
    const int mBase = blockIdx.y * BM + warpM * 32;
    const int nBase = blockIdx.x * BN + warpN * 32;

    #pragma unroll
    for (int mt = 0; mt < 2; mt++) {
        const int r0 = mBase + mt * 16 + (lane >> 2);
        const int r1 = r0 + 8;
        const float ct0 = kz * g_rowsum[r0];
        const float ct1 = kz * g_rowsum[r1];
        float* o0 = out + (size_t)r0 * N_TOT;
        float* o1 = out + (size_t)r1 * N_TOT;
        #pragma unroll
        for (int nt = 0; nt < 4; nt++) {
            const int col = nBase + nt * 8 + 2 * (lane & 3);
            const float2 bv = *reinterpret_cast<const float2*>(bias + col);
            float2 v0, v1;
            v0.x = fmaf(scale, acc[mt][nt][0], ct0 + bv.x);
            v0.y = fmaf(scale, acc[mt][nt][1], ct0 + bv.y);
            v1.x = fmaf(scale, acc[mt][nt][2], ct1 + bv.x);
            v1.y = fmaf(scale, acc[mt][nt][3], ct1 + bv.y);
            *reinterpret_cast<float2*>(o0 + col) = v0;
            *reinterpret_cast<float2*>(o1 + col) = v1;
        }
    }
}

// ---------------------------------------------------------------------------
extern "C" void kernel_launch(void* const* d_in, const int* in_sizes, int n_in,
                              void* d_out, int out_size) {
    const float* x     = (const float*)d_in[0];
    const int*   q     = (const int*)d_in[1];
    const float* scale = (const float*)d_in[2];
    const float* zp    = (const float*)d_in[3];
    const float* bias  = (const float*)d_in[4];
    float* out = (float*)d_out;

    cudaFuncSetAttribute(gemm_kernel,
                         cudaFuncAttributeMaxDynamicSharedMemorySize, DYN_SMEM);

    prep_kernel<<<M_TOT + (K_TOT / 32) * (N_TOT / 32), 256>>>(x, q);
    gemm_kernel<<<dim3(N_TOT / BN, M_TOT / BM), NTHREADS, DYN_SMEM>>>(
        scale, zp, bias, out);
}

// round 7
// speedup vs baseline: 1.1412x; 1.1412x over previous
#include <cuda_runtime.h>
#include <cuda_fp16.h>
#include <cstdint>

// ============================================================================
// y[m,n] = sum_k x[m,k] * ((q[k,n]-zp)*scale) + bias[n]
// Decomposition: W = scale*(q-128) + scale*(128-zp);  (q-128) exact in fp16.
// R7: revert to R4 CTA structure (256 thr, 128x128 tile, warp tile 64x32,
//     3-stage cp.async, 2 CTAs/SM) + split-K=2 (2048 CTAs -> 6.92 waves,
//     1.2% tail waste vs 13.5%) + epilogue via red.global.add.f32 into an
//     out[] pre-initialized by prep with bias + affine rowsum term.
//     Also: next-stage cp.async issued after ks=0 MMAs (hide issue bubble).
// ============================================================================

#define M_TOT 4096
#define N_TOT 4096
#define K_TOT 4096

__device__ __align__(256) __half g_A[(size_t)M_TOT * K_TOT]; // x fp16 [M,K]
__device__ __align__(256) __half g_B[(size_t)N_TOT * K_TOT]; // (q-128) fp16 [N,K]

// ---------------------------------------------------------------------------
__device__ __forceinline__ uint32_t smem_to_u32(const void* p) {
    uint32_t a;
    asm("{ .reg .u64 t; cvta.to.shared.u64 t, %1; cvt.u32.u64 %0, t; }"
        : "=r"(a) : "l"(p));
    return a;
}

#define SWZ(o) ((o) ^ (((o) >> 3) & 0x70))

#define CP_ASYNC_16(dst, src) \
    asm volatile("cp.async.cg.shared.global [%0], [%1], 16;" \
                 :: "r"(dst), "l"(src) : "memory")
#define CP_COMMIT() asm volatile("cp.async.commit_group;" ::: "memory")
#define CP_WAIT(n)  asm volatile("cp.async.wait_group %0;" :: "n"(n) : "memory")

#define LDSM_X4(R0, R1, R2, R3, ADDR) \
    asm volatile("ldmatrix.sync.aligned.m8n8.x4.shared.b16 {%0,%1,%2,%3}, [%4];" \
                 : "=r"(R0), "=r"(R1), "=r"(R2), "=r"(R3) : "r"(ADDR))

#define MMA16816(C, A0, A1, A2, A3, B0, B1) \
    asm volatile("mma.sync.aligned.m16n8k16.row.col.f32.f16.f16.f32 " \
                 "{%0,%1,%2,%3}, {%4,%5,%6,%7}, {%8,%9}, {%0,%1,%2,%3};" \
                 : "+f"((C)[0]), "+f"((C)[1]), "+f"((C)[2]), "+f"((C)[3]) \
                 : "r"(A0), "r"(A1), "r"(A2), "r"(A3), "r"(B0), "r"(B1))

#define REDG_ADD_F32(addr, val) \
    asm volatile("red.global.add.f32 [%0], %1;" :: "l"(addr), "f"(val) : "memory")

// ---------------------------------------------------------------------------
// Merged prep:
//  blocks [0,4096): convert x row -> fp16, compute rowsum, and initialize
//                   out[m][:] = scale*(128-zp)*rowsum[m] + bias[:]
//  blocks [4096, 4096+16384): transpose+convert 32x32 tiles of W.
// ---------------------------------------------------------------------------
__global__ void prep_kernel(const float* __restrict__ x,
                            const int* __restrict__ W,
                            const float* __restrict__ scale_p,
                            const float* __restrict__ zp_p,
                            const float* __restrict__ bias,
                            float* __restrict__ out) {
    __shared__ float red[256];
    __shared__ __half tile[32][33];
    const int tid = threadIdx.x;

    if (blockIdx.x < M_TOT) {
        const int m = blockIdx.x;
        const float4* xr = reinterpret_cast<const float4*>(x + (size_t)m * K_TOT);
        __half2* ar = reinterpret_cast<__half2*>(g_A + (size_t)m * K_TOT);
        float s = 0.0f;
        for (int i = tid; i < K_TOT / 4; i += 256) {
            float4 v = xr[i];
            ar[2 * i]     = __floats2half2_rn(v.x, v.y);
            ar[2 * i + 1] = __floats2half2_rn(v.z, v.w);
            s += (v.x + v.y) + (v.z + v.w);
        }
        red[tid] = s;
        __syncthreads();
        for (int o = 128; o > 0; o >>= 1) {
            if (tid < o) red[tid] += red[tid + o];
            __syncthreads();
        }
        // all threads: init out row with affine term + bias
        const float ct = scale_p[0] * (128.0f - zp_p[0]) * red[0];
        const float4* b4 = reinterpret_cast<const float4*>(bias);
        float4* o4 = reinterpret_cast<float4*>(out + (size_t)m * N_TOT);
        for (int i = tid; i < N_TOT / 4; i += 256) {
            float4 bv = b4[i];
            bv.x += ct; bv.y += ct; bv.z += ct; bv.w += ct;
            o4[i] = bv;
        }
    } else {
        const int t  = blockIdx.x - M_TOT;
        const int n0 = (t & (N_TOT / 32 - 1)) * 32;
        const int k0 = (t >> 7) * 32;
        const int tx = tid & 31, ty = tid >> 5;  // 32 x 8
        #pragma unroll
        for (int j = 0; j < 32; j += 8) {
            int k = k0 + ty + j;
            int n = n0 + tx;
            tile[ty + j][tx] = __int2half_rn(W[(size_t)k * N_TOT + n] - 128);
        }
        __syncthreads();
        #pragma unroll
        for (int j = 0; j < 32; j += 8) {
            int n = n0 + ty + j;
            int k = k0 + tx;
            g_B[(size_t)n * K_TOT + k] = tile[tx][ty + j];
        }
    }
}

// ---------------------------------------------------------------------------
// GEMM: BM=128, BN=128, split-K=2 (blockIdx.z), BK=64, 3-stage cp.async,
// 8 warps, 2 CTAs/SM. Warp grid 2(M) x 4(N); warp tile 64x32.
// Epilogue: red.global.add of scale*acc into pre-initialized out.
// ---------------------------------------------------------------------------
static constexpr int BM = 128;
static constexpr int BN = 128;
static constexpr int BK = 64;           // 128 bytes per row
static constexpr int STAGES = 3;
static constexpr int KSPLIT = 2;
static constexpr int KSEG   = K_TOT / KSPLIT;            // 2048
static constexpr int NCHUNK = KSEG / BK;                 // 32
static constexpr int A_BYTES   = BM * 128;               // 16384
static constexpr int B_BYTES   = BN * 128;               // 16384
static constexpr int STG_BYTES = A_BYTES + B_BYTES;      // 32768
static constexpr int DYN_SMEM  = 1024 + STAGES * STG_BYTES;  // 99328
static constexpr int A_JOBS = BM * 8;                    // 1024 x 16B
static constexpr int JOBS   = (BM + BN) * 8;             // 2048 x 16B

__global__ __launch_bounds__(256, 2)
void gemm_kernel(const float* __restrict__ scale_p,
                 float* __restrict__ out) {
    extern __shared__ char dyn_smem[];
    const uint32_t base = (smem_to_u32(dyn_smem) + 1023u) & ~1023u;

    const int tid  = threadIdx.x;
    const int lane = tid & 31;
    const int wid  = tid >> 5;
    const int warpM = wid & 1;    // 0..1 (64 rows each)
    const int warpN = wid >> 1;   // 0..3 (32 cols each)

    const int kbase = blockIdx.z * KSEG;
    const __half* Abase = g_A + (size_t)(blockIdx.y * BM) * K_TOT + kbase;
    const __half* Bbase = g_B + (size_t)(blockIdx.x * BN) * K_TOT + kbase;

    const int rowA = lane & 15;                       // A rows within m16
    const int khA  = (lane >> 4) * 8;                 // A k-half
    const int rowB = (lane & 7) + ((lane & 16) >> 1); // B n within n16
    const int khB  = ((lane >> 3) & 1) * 8;           // B k-half

    float acc[4][4][4];  // [mt 4 x m16][nt 4 x n8][frag]
    #pragma unroll
    for (int i = 0; i < 4; i++)
        #pragma unroll
        for (int j = 0; j < 4; j++)
            #pragma unroll
            for (int t = 0; t < 4; t++) acc[i][j][t] = 0.0f;

    auto load_stage = [&](int c, int st) {
        const int kofs = c * BK;
        const uint32_t sa = base + (uint32_t)st * STG_BYTES;
        const uint32_t sb = sa + A_BYTES;
        #pragma unroll
        for (int j = tid; j < JOBS; j += 256) {
            if (j < A_JOBS) {
                int r = j >> 3, cc = j & 7;
                uint32_t dst = sa + SWZ((uint32_t)(r * 128 + cc * 16));
                CP_ASYNC_16(dst, Abase + (size_t)r * K_TOT + kofs + cc * 8);
            } else {
                int jj = j - A_JOBS;
                int r = jj >> 3, cc = jj & 7;
                uint32_t dst = sb + SWZ((uint32_t)(r * 128 + cc * 16));
                CP_ASYNC_16(dst, Bbase + (size_t)r * K_TOT + kofs + cc * 8);
            }
        }
    };

    // prologue: fill STAGES-1 = 2 stages
    #pragma unroll
    for (int s = 0; s < STAGES - 1; s++) {
        load_stage(s, s);
        CP_COMMIT();
    }

    int st = 0, pst = STAGES - 1;
    for (int c = 0; c < NCHUNK; c++) {
        CP_WAIT(STAGES - 2);
        __syncthreads();   // all reads of stage pst complete; stage st ready

        const uint32_t sa = base + (uint32_t)st * STG_BYTES;
        const uint32_t sb = sa + A_BYTES;

        #pragma unroll
        for (int ks = 0; ks < 4; ks++) {
            uint32_t b[2][4];
            #pragma unroll
            for (int q = 0; q < 2; q++) {
                uint32_t off = (uint32_t)((warpN * 32 + q * 16 + rowB) * 128 +
                                          (ks * 16 + khB) * 2);
                LDSM_X4(b[q][0], b[q][1], b[q][2], b[q][3], sb + SWZ(off));
            }
            #pragma unroll
            for (int mt = 0; mt < 4; mt++) {
                uint32_t a0, a1, a2, a3;
                uint32_t off = (uint32_t)((warpM * 64 + mt * 16 + rowA) * 128 +
                                          (ks * 16 + khA) * 2);
                LDSM_X4(a0, a1, a2, a3, sa + SWZ(off));
                #pragma unroll
                for (int q = 0; q < 2; q++) {
                    MMA16816(acc[mt][2 * q],     a0, a1, a2, a3, b[q][0], b[q][1]);
                    MMA16816(acc[mt][2 * q + 1], a0, a1, a2, a3, b[q][2], b[q][3]);
                }
            }
            // issue next-stage loads AFTER the first ks of MMAs: the tensor
            // pipe is already fed, cp.async issue slots fill the gaps.
            if (ks == 0) {
                if (c + STAGES - 1 < NCHUNK) load_stage(c + STAGES - 1, pst);
                CP_COMMIT();
            }
        }
        pst = st;
        st = (st + 1 == STAGES) ? 0 : st + 1;
    }

    // ---- epilogue: red.global.add scale*acc into pre-initialized out ----
    const float scale = scale_p[0];
    const int mBase = blockIdx.y * BM + warpM * 64;
    const int nBase = blockIdx.x * BN + warpN * 32;

    #pragma unroll
    for (int mt = 0; mt < 4; mt++) {
        const int r0 = mBase + mt * 16 + (lane >> 2);
        const int r1 = r0 + 8;
        float* o0 = out + (size_t)r0 * N_TOT;
        float* o1 = out + (size_t)r1 * N_TOT;
        #pragma unroll
        for (int nt = 0; nt < 4; nt++) {
            const int col = nBase + nt * 8 + 2 * (lane & 3);
            REDG_ADD_F32(o0 + col,     scale * acc[mt][nt][0]);
            REDG_ADD_F32(o0 + col + 1, scale * acc[mt][nt][1]);
            REDG_ADD_F32(o1 + col,     scale * acc[mt][nt][2]);
            REDG_ADD_F32(o1 + col + 1, scale * acc[mt][nt][3]);
        }
    }
}

// ---------------------------------------------------------------------------
extern "C" void kernel_launch(void* const* d_in, const int* in_sizes, int n_in,
                              void* d_out, int out_size) {
    const float* x     = (const float*)d_in[0];
    const int*   q     = (const int*)d_in[1];
    const float* scale = (const float*)d_in[2];
    const float* zp    = (const float*)d_in[3];
    const float* bias  = (const float*)d_in[4];
    float* out = (float*)d_out;

    cudaFuncSetAttribute(gemm_kernel,
                         cudaFuncAttributeMaxDynamicSharedMemorySize, DYN_SMEM);

    prep_kernel<<<M_TOT + (K_TOT / 32) * (N_TOT / 32), 256>>>(
        x, q, scale, zp, bias, out);
    gemm_kernel<<<dim3(N_TOT / BN, M_TOT / BM, KSPLIT), 256, DYN_SMEM>>>(
        scale, out);
}

// round 8
// speedup vs baseline: 1.2571x; 1.1015x over previous
#include <cuda_runtime.h>
#include <cuda_fp16.h>
#include <cstdint>

// ============================================================================
// y[m,n] = sum_k x[m,k] * ((q[k,n]-zp)*scale) + bias[n]
// Decomposition: W = scale*(q-128) + scale*(128-zp);  (q-128) exact in fp16.
//   acc = half(x) @ half(q-128)   (fp32 accum via mma.sync HMMA)
//   y = scale*acc + scale*(128-zp)*rowsum(x)[m] + bias[n]
// R8 = R4 (best measured: 256 thr, 128x128 tile, warp tile 64x32, 3-stage
//      cp.async, 2 CTAs/SM, direct epilogue) + ONE change: next-stage
//      cp.async issue deferred until after the ks=0 MMA block, so the
//      tensor pipe refills immediately after the chunk barrier.
// ============================================================================

#define M_TOT 4096
#define N_TOT 4096
#define K_TOT 4096

__device__ __align__(256) __half g_A[(size_t)M_TOT * K_TOT]; // x fp16 [M,K]
__device__ __align__(256) __half g_B[(size_t)N_TOT * K_TOT]; // (q-128) fp16 [N,K]
__device__ float g_rowsum[M_TOT];

// ---------------------------------------------------------------------------
__device__ __forceinline__ uint32_t smem_to_u32(const void* p) {
    uint32_t a;
    asm("{ .reg .u64 t; cvta.to.shared.u64 t, %1; cvt.u32.u64 %0, t; }"
        : "=r"(a) : "l"(p));
    return a;
}

#define SWZ(o) ((o) ^ (((o) >> 3) & 0x70))

#define CP_ASYNC_16(dst, src) \
    asm volatile("cp.async.cg.shared.global [%0], [%1], 16;" \
                 :: "r"(dst), "l"(src) : "memory")
#define CP_COMMIT() asm volatile("cp.async.commit_group;" ::: "memory")
#define CP_WAIT(n)  asm volatile("cp.async.wait_group %0;" :: "n"(n) : "memory")

#define LDSM_X4(R0, R1, R2, R3, ADDR) \
    asm volatile("ldmatrix.sync.aligned.m8n8.x4.shared.b16 {%0,%1,%2,%3}, [%4];" \
                 : "=r"(R0), "=r"(R1), "=r"(R2), "=r"(R3) : "r"(ADDR))

#define MMA16816(C, A0, A1, A2, A3, B0, B1) \
    asm volatile("mma.sync.aligned.m16n8k16.row.col.f32.f16.f16.f32 " \
                 "{%0,%1,%2,%3}, {%4,%5,%6,%7}, {%8,%9}, {%0,%1,%2,%3};" \
                 : "+f"((C)[0]), "+f"((C)[1]), "+f"((C)[2]), "+f"((C)[3]) \
                 : "r"(A0), "r"(A1), "r"(A2), "r"(A3), "r"(B0), "r"(B1))

// ---------------------------------------------------------------------------
// Merged prep: blocks [0,4096) convert x rows + rowsum; blocks [4096, 20480)
// transpose+convert 32x32 tiles of W.
// ---------------------------------------------------------------------------
__global__ void prep_kernel(const float* __restrict__ x,
                            const int* __restrict__ W) {
    __shared__ float red[256];
    __shared__ __half tile[32][33];
    const int tid = threadIdx.x;

    if (blockIdx.x < M_TOT) {
        const int m = blockIdx.x;
        const float4* xr = reinterpret_cast<const float4*>(x + (size_t)m * K_TOT);
        __half2* ar = reinterpret_cast<__half2*>(g_A + (size_t)m * K_TOT);
        float s = 0.0f;
        for (int i = tid; i < K_TOT / 4; i += 256) {
            float4 v = xr[i];
            ar[2 * i]     = __floats2half2_rn(v.x, v.y);
            ar[2 * i + 1] = __floats2half2_rn(v.z, v.w);
            s += (v.x + v.y) + (v.z + v.w);
        }
        red[tid] = s;
        __syncthreads();
        for (int o = 128; o > 0; o >>= 1) {
            if (tid < o) red[tid] += red[tid + o];
            __syncthreads();
        }
        if (tid == 0) g_rowsum[m] = red[0];
    } else {
        const int t  = blockIdx.x - M_TOT;
        const int n0 = (t & (N_TOT / 32 - 1)) * 32;
        const int k0 = (t >> 7) * 32;
        const int tx = tid & 31, ty = tid >> 5;  // 32 x 8
        #pragma unroll
        for (int j = 0; j < 32; j += 8) {
            int k = k0 + ty + j;
            int n = n0 + tx;
            tile[ty + j][tx] = __int2half_rn(W[(size_t)k * N_TOT + n] - 128);
        }
        __syncthreads();
        #pragma unroll
        for (int j = 0; j < 32; j += 8) {
            int n = n0 + ty + j;
            int k = k0 + tx;
            g_B[(size_t)n * K_TOT + k] = tile[tx][ty + j];
        }
    }
}

// ---------------------------------------------------------------------------
// GEMM: BM=128, BN=128, BK=64, 3-stage cp.async pipeline, 8 warps, 2 CTAs/SM.
// Warp grid 2(M) x 4(N); warp tile 64x32; mma.sync m16n8k16 f32 accum.
// ---------------------------------------------------------------------------
static constexpr int BM = 128;
static constexpr int BN = 128;
static constexpr int BK = 64;           // 128 bytes per row
static constexpr int STAGES = 3;
static constexpr int NCHUNK = K_TOT / BK;                // 64
static constexpr int A_BYTES   = BM * 128;               // 16384
static constexpr int B_BYTES   = BN * 128;               // 16384
static constexpr int STG_BYTES = A_BYTES + B_BYTES;      // 32768
static constexpr int DYN_SMEM  = 1024 + STAGES * STG_BYTES;  // 99328
static constexpr int A_JOBS = BM * 8;                    // 1024 x 16B
static constexpr int JOBS   = (BM + BN) * 8;             // 2048 x 16B

__global__ __launch_bounds__(256, 2)
void gemm_kernel(const float* __restrict__ scale_p,
                 const float* __restrict__ zp_p,
                 const float* __restrict__ bias,
                 float* __restrict__ out) {
    extern __shared__ char dyn_smem[];
    const uint32_t base = (smem_to_u32(dyn_smem) + 1023u) & ~1023u;

    const int tid  = threadIdx.x;
    const int lane = tid & 31;
    const int wid  = tid >> 5;
    const int warpM = wid & 1;    // 0..1 (64 rows each)
    const int warpN = wid >> 1;   // 0..3 (32 cols each)

    const __half* Abase = g_A + (size_t)(blockIdx.y * BM) * K_TOT;
    const __half* Bbase = g_B + (size_t)(blockIdx.x * BN) * K_TOT;

    const int rowA = lane & 15;                       // A rows within m16
    const int khA  = (lane >> 4) * 8;                 // A k-half
    const int rowB = (lane & 7) + ((lane & 16) >> 1); // B n within n16
    const int khB  = ((lane >> 3) & 1) * 8;           // B k-half

    float acc[4][4][4];  // [mt 4 x m16][nt 4 x n8][frag]
    #pragma unroll
    for (int i = 0; i < 4; i++)
        #pragma unroll
        for (int j = 0; j < 4; j++)
            #pragma unroll
            for (int t = 0; t < 4; t++) acc[i][j][t] = 0.0f;

    auto load_stage = [&](int c, int st) {
        const int kofs = c * BK;
        const uint32_t sa = base + (uint32_t)st * STG_BYTES;
        const uint32_t sb = sa + A_BYTES;
        #pragma unroll
        for (int j = tid; j < JOBS; j += 256) {
            if (j < A_JOBS) {
                int r = j >> 3, cc = j & 7;
                uint32_t dst = sa + SWZ((uint32_t)(r * 128 + cc * 16));
                CP_ASYNC_16(dst, Abase + (size_t)r * K_TOT + kofs + cc * 8);
            } else {
                int jj = j - A_JOBS;
                int r = jj >> 3, cc = jj & 7;
                uint32_t dst = sb + SWZ((uint32_t)(r * 128 + cc * 16));
                CP_ASYNC_16(dst, Bbase + (size_t)r * K_TOT + kofs + cc * 8);
            }
        }
    };

    // prologue: fill STAGES-1 = 2 stages
    #pragma unroll
    for (int s = 0; s < STAGES - 1; s++) {
        load_stage(s, s);
        CP_COMMIT();
    }

    int st = 0, pst = STAGES - 1;
    for (int c = 0; c < NCHUNK; c++) {
        CP_WAIT(STAGES - 2);
        __syncthreads();   // all reads of stage pst complete; stage st ready

        const uint32_t sa = base + (uint32_t)st * STG_BYTES;
        const uint32_t sb = sa + A_BYTES;

        #pragma unroll
        for (int ks = 0; ks < 4; ks++) {
            uint32_t b[2][4];
            #pragma unroll
            for (int q = 0; q < 2; q++) {
                uint32_t off = (uint32_t)((warpN * 32 + q * 16 + rowB) * 128 +
                                          (ks * 16 + khB) * 2);
                LDSM_X4(b[q][0], b[q][1], b[q][2], b[q][3], sb + SWZ(off));
            }
            #pragma unroll
            for (int mt = 0; mt < 4; mt++) {
                uint32_t a0, a1, a2, a3;
                uint32_t off = (uint32_t)((warpM * 64 + mt * 16 + rowA) * 128 +
                                          (ks * 16 + khA) * 2);
                LDSM_X4(a0, a1, a2, a3, sa + SWZ(off));
                #pragma unroll
                for (int q = 0; q < 2; q++) {
                    MMA16816(acc[mt][2 * q],     a0, a1, a2, a3, b[q][0], b[q][1]);
                    MMA16816(acc[mt][2 * q + 1], a0, a1, a2, a3, b[q][2], b[q][3]);
                }
            }
            // Deferred next-stage copy: issued only after ks=0's MMAs so the
            // tensor pipe is refilled right after the chunk barrier.
            if (ks == 0) {
                if (c + STAGES - 1 < NCHUNK) load_stage(c + STAGES - 1, pst);
                CP_COMMIT();
            }
        }
        pst = st;
        st = (st + 1 == STAGES) ? 0 : st + 1;
    }

    // ---- epilogue ----
    const float scale = scale_p[0];
    const float zp    = zp_p[0];
    const float kz    = scale * (128.0f - zp);
    const int mBase = blockIdx.y * BM + warpM * 64;
    const int nBase = blockIdx.x * BN + warpN * 32;

    #pragma unroll
    for (int mt = 0; mt < 4; mt++) {
        const int r0 = mBase + mt * 16 + (lane >> 2);
        const int r1 = r0 + 8;
        const float ct0 = kz * g_rowsum[r0];
        const float ct1 = kz * g_rowsum[r1];
        float* o0 = out + (size_t)r0 * N_TOT;
        float* o1 = out + (size_t)r1 * N_TOT;
        #pragma unroll
        for (int nt = 0; nt < 4; nt++) {
            const int col = nBase + nt * 8 + 2 * (lane & 3);
            const float2 bv = *reinterpret_cast<const float2*>(bias + col);
            float2 v0, v1;
            v0.x = fmaf(scale, acc[mt][nt][0], ct0 + bv.x);
            v0.y = fmaf(scale, acc[mt][nt][1], ct0 + bv.y);
            v1.x = fmaf(scale, acc[mt][nt][2], ct1 + bv.x);
            v1.y = fmaf(scale, acc[mt][nt][3], ct1 + bv.y);
            *reinterpret_cast<float2*>(o0 + col) = v0;
            *reinterpret_cast<float2*>(o1 + col) = v1;
        }
    }
}

// ---------------------------------------------------------------------------
extern "C" void kernel_launch(void* const* d_in, const int* in_sizes, int n_in,
                              void* d_out, int out_size) {
    const float* x     = (const float*)d_in[0];
    const int*   q     = (const int*)d_in[1];
    const float* scale = (const float*)d_in[2];
    const float* zp    = (const float*)d_in[3];
    const float* bias  = (const float*)d_in[4];
    float* out = (float*)d_out;

    cudaFuncSetAttribute(gemm_kernel,
                         cudaFuncAttributeMaxDynamicSharedMemorySize, DYN_SMEM);

    prep_kernel<<<M_TOT + (K_TOT / 32) * (N_TOT / 32), 256>>>(x, q);
    gemm_kernel<<<dim3(N_TOT / BN, M_TOT / BM), 256, DYN_SMEM>>>(
        scale, zp, bias, out);
}

// round 10
// speedup vs baseline: 1.2713x; 1.0114x over previous
#include <cuda_runtime.h>
#include <cuda_fp16.h>
#include <cstdint>

// ============================================================================
// y[m,n] = sum_k x[m,k] * ((q[k,n]-zp)*scale) + bias[n]
// Decomposition: W = scale*(q-128) + scale*(128-zp);  (q-128) exact in fp16.
//   acc = half(x) @ half(q-128)   (fp32 accum via mma.sync HMMA)
//   y = scale*acc + scale*(128-zp)*rowsum(x)[m] + bias[n]
// R10 = R9 with the __half2_as_uint compile error fixed (bit-cast instead).
//   (1) B-fragment double-buffer across ks steps, (2) bandwidth-tuned prep.
// ============================================================================

#define M_TOT 4096
#define N_TOT 4096
#define K_TOT 4096

__device__ __align__(256) __half g_A[(size_t)M_TOT * K_TOT]; // x fp16 [M,K]
__device__ __align__(256) __half g_B[(size_t)N_TOT * K_TOT]; // (q-128) fp16 [N,K]
__device__ float g_rowsum[M_TOT];

// ---------------------------------------------------------------------------
__device__ __forceinline__ uint32_t smem_to_u32(const void* p) {
    uint32_t a;
    asm("{ .reg .u64 t; cvta.to.shared.u64 t, %1; cvt.u32.u64 %0, t; }"
        : "=r"(a) : "l"(p));
    return a;
}

__device__ __forceinline__ uint32_t h2_bits(__half2 h) {
    return *reinterpret_cast<uint32_t*>(&h);
}

#define SWZ(o) ((o) ^ (((o) >> 3) & 0x70))

#define CP_ASYNC_16(dst, src) \
    asm volatile("cp.async.cg.shared.global [%0], [%1], 16;" \
                 :: "r"(dst), "l"(src) : "memory")
#define CP_COMMIT() asm volatile("cp.async.commit_group;" ::: "memory")
#define CP_WAIT(n)  asm volatile("cp.async.wait_group %0;" :: "n"(n) : "memory")

#define LDSM_X4(R0, R1, R2, R3, ADDR) \
    asm volatile("ldmatrix.sync.aligned.m8n8.x4.shared.b16 {%0,%1,%2,%3}, [%4];" \
                 : "=r"(R0), "=r"(R1), "=r"(R2), "=r"(R3) : "r"(ADDR))

#define MMA16816(C, A0, A1, A2, A3, B0, B1) \
    asm volatile("mma.sync.aligned.m16n8k16.row.col.f32.f16.f16.f32 " \
                 "{%0,%1,%2,%3}, {%4,%5,%6,%7}, {%8,%9}, {%0,%1,%2,%3};" \
                 : "+f"((C)[0]), "+f"((C)[1]), "+f"((C)[2]), "+f"((C)[3]) \
                 : "r"(A0), "r"(A1), "r"(A2), "r"(A3), "r"(B0), "r"(B1))

// ---------------------------------------------------------------------------
// Prep A: x rows -> fp16 (16B stores) + rowsum. One block per row.
// ---------------------------------------------------------------------------
__global__ void prep_x_kernel(const float* __restrict__ x) {
    __shared__ float red[256];
    const int tid = threadIdx.x;
    const int m = blockIdx.x;
    const float4* xr = reinterpret_cast<const float4*>(x + (size_t)m * K_TOT);
    uint4* ar = reinterpret_cast<uint4*>(g_A + (size_t)m * K_TOT);  // 8 halfs
    float s = 0.0f;
    for (int i = tid; i < K_TOT / 8; i += 256) {
        float4 v0 = xr[2 * i];
        float4 v1 = xr[2 * i + 1];
        uint4 o;
        o.x = h2_bits(__floats2half2_rn(v0.x, v0.y));
        o.y = h2_bits(__floats2half2_rn(v0.z, v0.w));
        o.z = h2_bits(__floats2half2_rn(v1.x, v1.y));
        o.w = h2_bits(__floats2half2_rn(v1.z, v1.w));
        ar[i] = o;
        s += (v0.x + v0.y) + (v0.z + v0.w) + (v1.x + v1.y) + (v1.z + v1.w);
    }
    red[tid] = s;
    __syncthreads();
    for (int o = 128; o > 0; o >>= 1) {
        if (tid < o) red[tid] += red[tid + o];
        __syncthreads();
    }
    if (tid == 0) g_rowsum[m] = red[0];
}

// ---------------------------------------------------------------------------
// Prep B: W int32 [K,N] -> fp16 (q-128) in [N,K]. 64x64 tiles, int2 loads,
// half2 stores. tile pad 66 keeps half2 alignment and conflict-free access.
// ---------------------------------------------------------------------------
__global__ void prep_w_kernel(const int* __restrict__ W) {
    __shared__ __half tile[64][66];
    const int tid = threadIdx.x;                 // 256 threads
    const int n0 = (blockIdx.x & (N_TOT / 64 - 1)) * 64;
    const int k0 = (blockIdx.x / (N_TOT / 64)) * 64;

    // Load: 64 rows(k) x 32 int2(n pairs).
    const int2* W2 = reinterpret_cast<const int2*>(W);
    #pragma unroll
    for (int j = 0; j < 8; j++) {
        int idx2 = j * 256 + tid;
        int kr = idx2 >> 5;          // 0..63
        int nc2 = idx2 & 31;         // 0..31 (pairs)
        int2 v = W2[((size_t)(k0 + kr) * N_TOT + n0) / 2 + nc2];
        tile[2 * nc2][kr]     = __int2half_rn(v.x - 128);
        tile[2 * nc2 + 1][kr] = __int2half_rn(v.y - 128);
    }
    __syncthreads();

    // Store: 64 rows(n) x 32 half2(k pairs).
    #pragma unroll
    for (int j = 0; j < 8; j++) {
        int idx2 = j * 256 + tid;
        int nr = idx2 >> 5;          // 0..63
        int kc2 = idx2 & 31;         // 0..31 (pairs)
        __half2 v = *reinterpret_cast<__half2*>(&tile[nr][2 * kc2]);
        *reinterpret_cast<__half2*>(
            g_B + (size_t)(n0 + nr) * K_TOT + k0 + 2 * kc2) = v;
    }
}

// ---------------------------------------------------------------------------
// GEMM: BM=128, BN=128, BK=64, 3-stage cp.async pipeline, 8 warps, 2 CTAs/SM.
// Warp grid 2(M) x 4(N); warp tile 64x32; mma.sync m16n8k16 f32 accum.
// B fragments double-buffered across ks; next-stage copy deferred to ks=0 end.
// ---------------------------------------------------------------------------
static constexpr int BM = 128;
static constexpr int BN = 128;
static constexpr int BK = 64;           // 128 bytes per row
static constexpr int STAGES = 3;
static constexpr int NCHUNK = K_TOT / BK;                // 64
static constexpr int A_BYTES   = BM * 128;               // 16384
static constexpr int B_BYTES   = BN * 128;               // 16384
static constexpr int STG_BYTES = A_BYTES + B_BYTES;      // 32768
static constexpr int DYN_SMEM  = 1024 + STAGES * STG_BYTES;  // 99328
static constexpr int A_JOBS = BM * 8;                    // 1024 x 16B
static constexpr int JOBS   = (BM + BN) * 8;             // 2048 x 16B

__global__ __launch_bounds__(256, 2)
void gemm_kernel(const float* __restrict__ scale_p,
                 const float* __restrict__ zp_p,
                 const float* __restrict__ bias,
                 float* __restrict__ out) {
    extern __shared__ char dyn_smem[];
    const uint32_t base = (smem_to_u32(dyn_smem) + 1023u) & ~1023u;

    const int tid  = threadIdx.x;
    const int lane = tid & 31;
    const int wid  = tid >> 5;
    const int warpM = wid & 1;    // 0..1 (64 rows each)
    const int warpN = wid >> 1;   // 0..3 (32 cols each)

    const __half* Abase = g_A + (size_t)(blockIdx.y * BM) * K_TOT;
    const __half* Bbase = g_B + (size_t)(blockIdx.x * BN) * K_TOT;

    const int rowA = lane & 15;                       // A rows within m16
    const int khA  = (lane >> 4) * 8;                 // A k-half
    const int rowB = (lane & 7) + ((lane & 16) >> 1); // B n within n16
    const int khB  = ((lane >> 3) & 1) * 8;           // B k-half

    float acc[4][4][4];  // [mt 4 x m16][nt 4 x n8][frag]
    #pragma unroll
    for (int i = 0; i < 4; i++)
        #pragma unroll
        for (int j = 0; j < 4; j++)
            #pragma unroll
            for (int t = 0; t < 4; t++) acc[i][j][t] = 0.0f;

    auto load_stage = [&](int c, int st) {
        const int kofs = c * BK;
        const uint32_t sa = base + (uint32_t)st * STG_BYTES;
        const uint32_t sb = sa + A_BYTES;
        #pragma unroll
        for (int j = tid; j < JOBS; j += 256) {
            if (j < A_JOBS) {
                int r = j >> 3, cc = j & 7;
                uint32_t dst = sa + SWZ((uint32_t)(r * 128 + cc * 16));
                CP_ASYNC_16(dst, Abase + (size_t)r * K_TOT + kofs + cc * 8);
            } else {
                int jj = j - A_JOBS;
                int r = jj >> 3, cc = jj & 7;
                uint32_t dst = sb + SWZ((uint32_t)(r * 128 + cc * 16));
                CP_ASYNC_16(dst, Bbase + (size_t)r * K_TOT + kofs + cc * 8);
            }
        }
    };

    // prologue: fill STAGES-1 = 2 stages
    #pragma unroll
    for (int s = 0; s < STAGES - 1; s++) {
        load_stage(s, s);
        CP_COMMIT();
    }

    int st = 0, pst = STAGES - 1;
    for (int c = 0; c < NCHUNK; c++) {
        CP_WAIT(STAGES - 2);
        __syncthreads();   // all reads of stage pst complete; stage st ready

        const uint32_t sa = base + (uint32_t)st * STG_BYTES;
        const uint32_t sb = sa + A_BYTES;

        // B fragments double-buffered across ks
        uint32_t bf[2][2][4];
        #pragma unroll
        for (int q = 0; q < 2; q++) {
            uint32_t off = (uint32_t)((warpN * 32 + q * 16 + rowB) * 128 + khB * 2);
            LDSM_X4(bf[0][q][0], bf[0][q][1], bf[0][q][2], bf[0][q][3],
                    sb + SWZ(off));
        }

        #pragma unroll
        for (int ks = 0; ks < 4; ks++) {
            const int cur = ks & 1;
            if (ks < 3) {
                const int nxt = cur ^ 1;
                #pragma unroll
                for (int q = 0; q < 2; q++) {
                    uint32_t off = (uint32_t)((warpN * 32 + q * 16 + rowB) * 128 +
                                              ((ks + 1) * 16 + khB) * 2);
                    LDSM_X4(bf[nxt][q][0], bf[nxt][q][1], bf[nxt][q][2],
                            bf[nxt][q][3], sb + SWZ(off));
                }
            }
            #pragma unroll
            for (int mt = 0; mt < 4; mt++) {
                uint32_t a0, a1, a2, a3;
                uint32_t off = (uint32_t)((warpM * 64 + mt * 16 + rowA) * 128 +
                                          (ks * 16 + khA) * 2);
                LDSM_X4(a0, a1, a2, a3, sa + SWZ(off));
                #pragma unroll
                for (int q = 0; q < 2; q++) {
                    MMA16816(acc[mt][2 * q],     a0, a1, a2, a3,
                             bf[cur][q][0], bf[cur][q][1]);
                    MMA16816(acc[mt][2 * q + 1], a0, a1, a2, a3,
                             bf[cur][q][2], bf[cur][q][3]);
                }
            }
            // Deferred next-stage copy after ks=0's MMAs.
            if (ks == 0) {
                if (c + STAGES - 1 < NCHUNK) load_stage(c + STAGES - 1, pst);
                CP_COMMIT();
            }
        }
        pst = st;
        st = (st + 1 == STAGES) ? 0 : st + 1;
    }

    // ---- epilogue ----
    const float scale = scale_p[0];
    const float zp    = zp_p[0];
    const float kz    = scale * (128.0f - zp);
    const int mBase = blockIdx.y * BM + warpM * 64;
    const int nBase = blockIdx.x * BN + warpN * 32;

    #pragma unroll
    for (int mt = 0; mt < 4; mt++) {
        const int r0 = mBase + mt * 16 + (lane >> 2);
        const int r1 = r0 + 8;
        const float ct0 = kz * g_rowsum[r0];
        const float ct1 = kz * g_rowsum[r1];
        float* o0 = out + (size_t)r0 * N_TOT;
        float* o1 = out + (size_t)r1 * N_TOT;
        #pragma unroll
        for (int nt = 0; nt < 4; nt++) {
            const int col = nBase + nt * 8 + 2 * (lane & 3);
            const float2 bv = *reinterpret_cast<const float2*>(bias + col);
            float2 v0, v1;
            v0.x = fmaf(scale, acc[mt][nt][0], ct0 + bv.x);
            v0.y = fmaf(scale, acc[mt][nt][1], ct0 + bv.y);
            v1.x = fmaf(scale, acc[mt][nt][2], ct1 + bv.x);
            v1.y = fmaf(scale, acc[mt][nt][3], ct1 + bv.y);
            *reinterpret_cast<float2*>(o0 + col) = v0;
            *reinterpret_cast<float2*>(o1 + col) = v1;
        }
    }
}

// ---------------------------------------------------------------------------
extern "C" void kernel_launch(void* const* d_in, const int* in_sizes, int n_in,
                              void* d_out, int out_size) {
    const float* x     = (const float*)d_in[0];
    const int*   q     = (const int*)d_in[1];
    const float* scale = (const float*)d_in[2];
    const float* zp    = (const float*)d_in[3];
    const float* bias  = (const float*)d_in[4];
    float* out = (float*)d_out;

    cudaFuncSetAttribute(gemm_kernel,
                         cudaFuncAttributeMaxDynamicSharedMemorySize, DYN_SMEM);

    prep_x_kernel<<<M_TOT, 256>>>(x);
    prep_w_kernel<<<(K_TOT / 64) * (N_TOT / 64), 256>>>(q);
    gemm_kernel<<<dim3(N_TOT / BN, M_TOT / BM), 256, DYN_SMEM>>>(
        scale, zp, bias, out);
}